// round 2
// baseline (speedup 1.0000x reference)
#include <cuda_runtime.h>
#include <cstdint>

// ---------------------------------------------------------------------------
// Problem constants
// ---------------------------------------------------------------------------
#define T_STEPS 2048
#define BATCH   64
#define INSZ    512
#define HID     256
#define G4      1024      // 4*HID
#define OUTSZ   128
#define MROWS   (T_STEPS * BATCH)   // 131072

// Scratch (device globals: allocation-free per harness rules)
__device__ float g_Xp[(size_t)MROWS * G4];   // input projection + biases, 512 MB
__device__ float g_hs[(size_t)MROWS * HID];  // hidden states, 128 MB

// ---------------------------------------------------------------------------
// GEMM (NT): C[m,n] = sum_k A[m,k] * B[n,k] + bias1[n] (+ bias2[n])
// BM=BN=128, BK=16, 256 threads, 8x8 register micro-tile.
// Requires M%128==0, N%128==0, K%16==0 (true for both uses).
// ---------------------------------------------------------------------------
__global__ void __launch_bounds__(256)
sgemm128(const float* __restrict__ A, const float* __restrict__ Bm,
         const float* __restrict__ bias1, const float* __restrict__ bias2,
         float* __restrict__ C, int K, int N)
{
    __shared__ float As[16][128];
    __shared__ float Bs[16][128];

    const int tid = threadIdx.x;
    const int tx = tid & 15;
    const int ty = tid >> 4;
    const size_t m0 = (size_t)blockIdx.x * 128;
    const int n0 = blockIdx.y * 128;

    const int lrow = tid >> 2;        // 0..63
    const int lk   = (tid & 3) * 4;   // 0,4,8,12

    const float* Ar0 = A  + (m0 + lrow) * (size_t)K + lk;
    const float* Ar1 = Ar0 + (size_t)64 * K;
    const float* Br0 = Bm + (size_t)(n0 + lrow) * K + lk;
    const float* Br1 = Br0 + (size_t)64 * K;

    float acc[8][8];
#pragma unroll
    for (int i = 0; i < 8; ++i)
#pragma unroll
        for (int j = 0; j < 8; ++j) acc[i][j] = 0.f;

    for (int k0 = 0; k0 < K; k0 += 16) {
        float4 a0 = *(const float4*)(Ar0 + k0);
        float4 a1 = *(const float4*)(Ar1 + k0);
        float4 b0 = *(const float4*)(Br0 + k0);
        float4 b1 = *(const float4*)(Br1 + k0);
        __syncthreads();
        As[lk+0][lrow]    = a0.x; As[lk+1][lrow]    = a0.y;
        As[lk+2][lrow]    = a0.z; As[lk+3][lrow]    = a0.w;
        As[lk+0][lrow+64] = a1.x; As[lk+1][lrow+64] = a1.y;
        As[lk+2][lrow+64] = a1.z; As[lk+3][lrow+64] = a1.w;
        Bs[lk+0][lrow]    = b0.x; Bs[lk+1][lrow]    = b0.y;
        Bs[lk+2][lrow]    = b0.z; Bs[lk+3][lrow]    = b0.w;
        Bs[lk+0][lrow+64] = b1.x; Bs[lk+1][lrow+64] = b1.y;
        Bs[lk+2][lrow+64] = b1.z; Bs[lk+3][lrow+64] = b1.w;
        __syncthreads();
#pragma unroll
        for (int kk = 0; kk < 16; ++kk) {
            float av[8], bv[8];
            *(float4*)&av[0] = *(const float4*)&As[kk][ty * 4];
            *(float4*)&av[4] = *(const float4*)&As[kk][ty * 4 + 64];
            *(float4*)&bv[0] = *(const float4*)&Bs[kk][tx * 4];
            *(float4*)&bv[4] = *(const float4*)&Bs[kk][tx * 4 + 64];
#pragma unroll
            for (int i = 0; i < 8; ++i)
#pragma unroll
                for (int j = 0; j < 8; ++j)
                    acc[i][j] = fmaf(av[i], bv[j], acc[i][j]);
        }
    }

    // bias
    float4 bb0 = *(const float4*)(bias1 + n0 + tx * 4);
    float4 bb1 = *(const float4*)(bias1 + n0 + tx * 4 + 64);
    if (bias2) {
        float4 c0 = *(const float4*)(bias2 + n0 + tx * 4);
        float4 c1 = *(const float4*)(bias2 + n0 + tx * 4 + 64);
        bb0.x += c0.x; bb0.y += c0.y; bb0.z += c0.z; bb0.w += c0.w;
        bb1.x += c1.x; bb1.y += c1.y; bb1.z += c1.z; bb1.w += c1.w;
    }

#pragma unroll
    for (int i = 0; i < 8; ++i) {
        size_t row = m0 + ty * 4 + (i < 4 ? i : 60 + i);
        float4 o0 = make_float4(acc[i][0] + bb0.x, acc[i][1] + bb0.y,
                                acc[i][2] + bb0.z, acc[i][3] + bb0.w);
        float4 o1 = make_float4(acc[i][4] + bb1.x, acc[i][5] + bb1.y,
                                acc[i][6] + bb1.z, acc[i][7] + bb1.w);
        *(float4*)(C + row * N + n0 + tx * 4)      = o0;
        *(float4*)(C + row * N + n0 + tx * 4 + 64) = o1;
    }
}

// ---------------------------------------------------------------------------
// LSTM recurrence: persistent clustered kernel.
// 16 clusters x 8 CTAs x 256 threads. Cluster cl owns batches [cl*4, cl*4+4).
// CTA rank r owns hidden indices j in [r*32, (r+1)*32) -> keeps the 128 W_hh
// rows {g*256 + r*32 + jj} (all 4 gates) in smem (128 KB, k-major).
// Per step: each warp covers a 32-wide K chunk; lane covers 4 gate-rows x 4
// batches; cross-warp reduction in smem; h broadcast to all 8 CTAs via DSMEM.
// ---------------------------------------------------------------------------
#define REC_SMEM_FLOATS (256*128 + 2*4*256 + 8*4*128 + 128)
#define REC_SMEM_BYTES  (REC_SMEM_FLOATS * 4)

__global__ void __launch_bounds__(256, 1)
lstm_rec_kernel(const float* __restrict__ Whh,
                const float* __restrict__ Xp,
                float* __restrict__ hs)
{
    extern __shared__ float sm[];
    float* wsm    = sm;                    // [k=256][lr=128]
    float* hsm    = wsm + 256 * 128;       // [2][b=4][k=256]
    float* part   = hsm + 2 * 4 * 256;     // [w=8][b=4][lr=128]
    float* hstage = part + 8 * 4 * 128;    // [128]

    const int tid  = threadIdx.x;
    const int lane = tid & 31;
    const int w    = tid >> 5;

    unsigned r;
    asm("mov.u32 %0, %%cluster_ctarank;" : "=r"(r));
    const int cl = blockIdx.x >> 3;

    // Load this CTA's W_hh slice, transposed to k-major: wsm[k*128 + lr]
    for (int idx = tid; idx < 128 * 64; idx += 256) {
        int lr = idx >> 6;                 // 0..127  (= g*32 + jj)
        int k4 = idx & 63;                 // float4 index along K
        int grow = ((lr >> 5) << 8) + (int)r * 32 + (lr & 31);
        float4 v = *(const float4*)(Whh + (size_t)grow * 256 + k4 * 4);
        wsm[(k4 * 4 + 0) * 128 + lr] = v.x;
        wsm[(k4 * 4 + 1) * 128 + lr] = v.y;
        wsm[(k4 * 4 + 2) * 128 + lr] = v.z;
        wsm[(k4 * 4 + 3) * 128 + lr] = v.w;
    }
    for (int i = tid; i < 4 * 256; i += 256) hsm[i] = 0.f;  // h0 = 0 (buffer 0)
    __syncthreads();

    const int bb = tid >> 5;   // for tid<128: batch 0..3
    const int jj = tid & 31;
    float c = 0.f;             // cell state lives in a register of tid<128

    for (int t = 0; t < T_STEPS; ++t) {
        const int cur = t & 1;
        const float4* hp = (const float4*)(hsm + cur * 1024);   // [b][64]
        const float4* wp = (const float4*)wsm;                  // [k][32]

        // Early-issue Xp loads (hidden behind the dot loop)
        float xq0 = 0.f, xq1 = 0.f, xq2 = 0.f, xq3 = 0.f;
        if (tid < 128) {
            const float* xp = Xp + ((size_t)t * 64 + cl * 4 + bb) * 1024
                                 + (int)r * 32 + jj;
            xq0 = xp[0]; xq1 = xp[256]; xq2 = xp[512]; xq3 = xp[768];
        }

        // Dot phase: this thread accumulates rows 4*lane..4*lane+3, batches
        // 0..3, over K chunk [w*32, w*32+32).
        float4 a0 = make_float4(0,0,0,0), a1 = a0, a2 = a0, a3 = a0;
#pragma unroll
        for (int kg = 0; kg < 8; ++kg) {
            int kgi = (w << 3) + kg;
            float4 wv0 = wp[(kgi * 4 + 0) * 32 + lane];
            float4 wv1 = wp[(kgi * 4 + 1) * 32 + lane];
            float4 wv2 = wp[(kgi * 4 + 2) * 32 + lane];
            float4 wv3 = wp[(kgi * 4 + 3) * 32 + lane];
            float4 h0 = hp[kgi];
            float4 h1 = hp[64 + kgi];
            float4 h2 = hp[128 + kgi];
            float4 h3 = hp[192 + kgi];
#define ACC4(A, HB) \
            A.x = fmaf(wv0.x, HB.x, A.x); A.x = fmaf(wv1.x, HB.y, A.x); \
            A.x = fmaf(wv2.x, HB.z, A.x); A.x = fmaf(wv3.x, HB.w, A.x); \
            A.y = fmaf(wv0.y, HB.x, A.y); A.y = fmaf(wv1.y, HB.y, A.y); \
            A.y = fmaf(wv2.y, HB.z, A.y); A.y = fmaf(wv3.y, HB.w, A.y); \
            A.z = fmaf(wv0.z, HB.x, A.z); A.z = fmaf(wv1.z, HB.y, A.z); \
            A.z = fmaf(wv2.z, HB.z, A.z); A.z = fmaf(wv3.z, HB.w, A.z); \
            A.w = fmaf(wv0.w, HB.x, A.w); A.w = fmaf(wv1.w, HB.y, A.w); \
            A.w = fmaf(wv2.w, HB.z, A.w); A.w = fmaf(wv3.w, HB.w, A.w);
            ACC4(a0, h0) ACC4(a1, h1) ACC4(a2, h2) ACC4(a3, h3)
#undef ACC4
        }
        // store partials: part[w][b][4*lane..4*lane+3]
        ((float4*)(part + (w * 4 + 0) * 128))[lane] = a0;
        ((float4*)(part + (w * 4 + 1) * 128))[lane] = a1;
        ((float4*)(part + (w * 4 + 2) * 128))[lane] = a2;
        ((float4*)(part + (w * 4 + 3) * 128))[lane] = a3;
        __syncthreads();

        // Reduction + gates (tid<128: one (jj, bb) pair each)
        if (tid < 128) {
            float s0 = xq0, s1 = xq1, s2 = xq2, s3 = xq3;
#pragma unroll
            for (int w8 = 0; w8 < 8; ++w8) {
                const float* p = part + (w8 * 4 + bb) * 128 + jj;
                s0 += p[0]; s1 += p[32]; s2 += p[64]; s3 += p[96];
            }
            float ig = 1.f / (1.f + __expf(-s0));
            float fg = 1.f / (1.f + __expf(-s1));
            float gg = tanhf(s2);
            float og = 1.f / (1.f + __expf(-s3));
            c = fg * c + ig * gg;
            float h = og * tanhf(c);
            hstage[bb * 32 + jj] = h;
            hs[((size_t)t * 64 + cl * 4 + bb) * 256 + (int)r * 32 + jj] = h;
        }
        __syncthreads();

        // DSMEM push: broadcast this CTA's 128 new h values (32 j x 4 b) into
        // every cluster CTA's hsm[next] (including self). 1 STS.128 per thread.
        {
            const int nxt = cur ^ 1;
            const unsigned dst = (unsigned)(tid >> 5);   // 0..7
            const int q = tid & 31;                      // float4 idx over 128
            float4 v = ((const float4*)hstage)[q];
            float* dp = hsm + nxt * 1024 + (q >> 3) * 256 + (int)r * 32 + ((q & 7) << 2);
            unsigned la = (unsigned)__cvta_generic_to_shared(dp);
            unsigned ra;
            asm volatile("mapa.shared::cluster.u32 %0, %1, %2;"
                         : "=r"(ra) : "r"(la), "r"(dst));
            asm volatile("st.shared::cluster.v4.f32 [%0], {%1,%2,%3,%4};"
                         :: "r"(ra), "f"(v.x), "f"(v.y), "f"(v.z), "f"(v.w)
                         : "memory");
        }
        // release(arrive) / acquire(wait): orders DSMEM stores for next step
        asm volatile("barrier.cluster.arrive.aligned;" ::: "memory");
        asm volatile("barrier.cluster.wait.aligned;"   ::: "memory");
    }
}

// ---------------------------------------------------------------------------
// Launch
// ---------------------------------------------------------------------------
extern "C" void kernel_launch(void* const* d_in, const int* in_sizes, int n_in,
                              void* d_out, int out_size)
{
    const float* inputs = (const float*)d_in[0];
    const float* W_ih   = (const float*)d_in[1];
    const float* W_hh   = (const float*)d_in[2];
    const float* b_ih   = (const float*)d_in[3];
    const float* b_hh   = (const float*)d_in[4];
    const float* W_fc   = (const float*)d_in[5];
    const float* b_fc   = (const float*)d_in[6];
    float* out = (float*)d_out;

    float *Xp, *hsbuf;
    cudaGetSymbolAddress((void**)&Xp, g_Xp);
    cudaGetSymbolAddress((void**)&hsbuf, g_hs);

    // 1) Xp = inputs @ W_ih^T + (b_ih + b_hh)   [131072 x 1024]
    {
        dim3 grid(MROWS / 128, G4 / 128);
        sgemm128<<<grid, 256>>>(inputs, W_ih, b_ih, b_hh, Xp, INSZ, G4);
    }

    // 2) LSTM recurrence (clustered persistent kernel) -> hs [131072 x 256]
    {
        cudaFuncSetAttribute(lstm_rec_kernel,
                             cudaFuncAttributeMaxDynamicSharedMemorySize,
                             REC_SMEM_BYTES);
        cudaLaunchConfig_t cfg = {};
        cfg.gridDim = dim3(128, 1, 1);
        cfg.blockDim = dim3(256, 1, 1);
        cfg.dynamicSmemBytes = REC_SMEM_BYTES;
        cfg.stream = 0;
        cudaLaunchAttribute attr[1];
        attr[0].id = cudaLaunchAttributeClusterDimension;
        attr[0].val.clusterDim.x = 8;
        attr[0].val.clusterDim.y = 1;
        attr[0].val.clusterDim.z = 1;
        cfg.attrs = attr;
        cfg.numAttrs = 1;
        cudaLaunchKernelEx(&cfg, lstm_rec_kernel, W_hh, (const float*)Xp, hsbuf);
    }

    // 3) out = hs @ W_fc^T + b_fc   [131072 x 128]
    {
        dim3 grid(MROWS / 128, OUTSZ / 128);
        sgemm128<<<grid, 256>>>(hsbuf, W_fc, b_fc, (const float*)nullptr, out,
                                HID, OUTSZ);
    }
}